// round 1
// baseline (speedup 1.0000x reference)
#include <cuda_runtime.h>
#include <cuda_fp16.h>

#define N_NODES 8192
#define IN_F 256
#define OUT_F 64
#define ALPHA 0.3f
#define MAXNZ 1024

// Scratch (no allocations allowed): fp16 Wh (uint4 for 16B-aligned vector loads),
// src/dst attention projections.
__device__ uint4 g_Whh[N_NODES * (OUT_F * 2 / 16)];  // 8192 * 8 uint4 = 1 MB
__device__ float g_src[N_NODES];
__device__ float g_dst[N_NODES];

// ---------------------------------------------------------------------------
// Kernel 1: Wh = h @ W (fp16 out), src = Wh @ a[:64], dst = Wh @ a[64:]
// One block per node row, 64 threads (one per output feature).
// ---------------------------------------------------------------------------
__global__ __launch_bounds__(64) void wh_kernel(const float* __restrict__ h,
                                                const float* __restrict__ W,
                                                const float* __restrict__ a) {
    __shared__ float hrow[IN_F];
    __shared__ float sred[2], dred[2];
    const int i = blockIdx.x;
    const int f = threadIdx.x;  // 0..63

    const float4* h4 = reinterpret_cast<const float4*>(h + (size_t)i * IN_F);
    reinterpret_cast<float4*>(hrow)[f] = h4[f];  // 64 threads * 4 = 256
    __syncthreads();

    float acc = 0.f;
#pragma unroll 8
    for (int k = 0; k < IN_F; k++) acc += hrow[k] * __ldg(&W[k * OUT_F + f]);

    reinterpret_cast<__half*>(g_Whh)[(size_t)i * OUT_F + f] = __float2half(acc);

    float sv = acc * __ldg(&a[f]);
    float dv = acc * __ldg(&a[OUT_F + f]);
#pragma unroll
    for (int o = 16; o; o >>= 1) {
        sv += __shfl_down_sync(0xffffffffu, sv, o);
        dv += __shfl_down_sync(0xffffffffu, dv, o);
    }
    if ((f & 31) == 0) { sred[f >> 5] = sv; dred[f >> 5] = dv; }
    __syncthreads();
    if (f == 0) {
        g_src[i] = sred[0] + sred[1];
        g_dst[i] = dred[0] + dred[1];
    }
}

// ---------------------------------------------------------------------------
// Kernel 2: fused masked-softmax attention + aggregation + ELU.
// One block (256 threads = 8 warps) per row i.
//   A: stream adj row once -> 256-word bitmask (ballot)
//   B: deterministic compaction (prefix scan) -> sorted nz list; e/max/exp/sum
//   C: gather-aggregate: warp handles 4 nz/iter, 8 lanes x uint4 (8 fp16) each
// ---------------------------------------------------------------------------
__global__ __launch_bounds__(256) void attn_kernel(const float* __restrict__ adj,
                                                   float* __restrict__ out) {
    const int i = blockIdx.x;
    const int tid = threadIdx.x;
    const int w = tid >> 5;
    const int lane = tid & 31;

    __shared__ unsigned mask[256];
    __shared__ int wsum[8], wbase[8];
    __shared__ float fred[8];
    __shared__ int cnt_s;
    __shared__ float rowmax_s, invden_s;
    __shared__ unsigned short jlist[MAXNZ];
    __shared__ float plist[MAXNZ];
    __shared__ float acc_red[32][OUT_F];
    __shared__ float fin[4][OUT_F];

    const float srci = g_src[i];
    const float* adjrow = adj + (size_t)i * N_NODES;

    // ---- Phase A: bitmask from adj (the ONLY read of adj) ----
#pragma unroll 4
    for (int k = 0; k < 32; k++) {
        const int word = (k << 3) + w;  // 0..255
        const float av = __ldg(&adjrow[(word << 5) + lane]);
        const unsigned bal = __ballot_sync(0xffffffffu, av != 0.f);
        if (lane == 0) mask[word] = bal;
    }
    __syncthreads();

    // ---- deterministic compaction: exclusive scan of per-word popcounts ----
    const int c = __popc(mask[tid]);
    int incl = c;
#pragma unroll
    for (int o = 1; o < 32; o <<= 1) {
        const int x = __shfl_up_sync(0xffffffffu, incl, o);
        if (lane >= o) incl += x;
    }
    if (lane == 31) wsum[w] = incl;
    __syncthreads();
    if (tid == 0) {
        int run = 0;
        for (int q = 0; q < 8; q++) { wbase[q] = run; run += wsum[q]; }
        cnt_s = run < MAXNZ ? run : MAXNZ;
    }
    __syncthreads();
    {
        int off = wbase[w] + incl - c;
        unsigned m = mask[tid];
        const int basej = tid << 5;
        while (m) {
            const int b = __ffs(m) - 1;
            m &= m - 1;
            if (off < MAXNZ) jlist[off] = (unsigned short)(basej + b);
            off++;
        }
    }
    __syncthreads();
    const int cnt = cnt_s;

    // ---- Phase B1: logits + row max ----
    float lmax = -3.0e38f;
    for (int idx = tid; idx < cnt; idx += 256) {
        const int j = jlist[idx];
        float e = srci + __ldg(&g_dst[j]);
        e = e > 0.f ? e : ALPHA * e;
        plist[idx] = e;
        lmax = fmaxf(lmax, e);
    }
#pragma unroll
    for (int o = 16; o; o >>= 1) lmax = fmaxf(lmax, __shfl_xor_sync(0xffffffffu, lmax, o));
    if (lane == 0) fred[w] = lmax;
    __syncthreads();
    if (tid == 0) {
        float mm = fred[0];
        for (int q = 1; q < 8; q++) mm = fmaxf(mm, fred[q]);
        rowmax_s = mm;
    }
    __syncthreads();
    const float rowmax = rowmax_s;

    // ---- Phase B2: exp + denom ----
    float lsum = 0.f;
    for (int idx = tid; idx < cnt; idx += 256) {
        const float p = __expf(plist[idx] - rowmax);
        plist[idx] = p;
        lsum += p;
    }
#pragma unroll
    for (int o = 16; o; o >>= 1) lsum += __shfl_xor_sync(0xffffffffu, lsum, o);
    if (lane == 0) fred[w] = lsum;
    __syncthreads();
    if (tid == 0) {
        float s = 0.f;
        for (int q = 0; q < 8; q++) s += fred[q];
        invden_s = 1.f / s;
    }
    __syncthreads();

    // ---- Phase C: h' = sum_j p_j * Wh[j]  (fp16 gather, fp32 accumulate) ----
    const int g = lane >> 3;   // 4 nz-groups per warp
    const int s8 = lane & 7;   // 8 lanes x 8 halves = 64 features
    float acc[8];
#pragma unroll
    for (int q = 0; q < 8; q++) acc[q] = 0.f;

    for (int base = (w << 2); base < cnt; base += 32) {
        const int idx = base + g;
        float p = 0.f;
        int j = 0;
        if (idx < cnt) { p = plist[idx]; j = jlist[idx]; }
        const uint4 v = __ldg(&g_Whh[j * 8 + s8]);
        const __half2* hv = reinterpret_cast<const __half2*>(&v);
#pragma unroll
        for (int q = 0; q < 4; q++) {
            const float2 f2 = __half22float2(hv[q]);
            acc[2 * q]     += p * f2.x;
            acc[2 * q + 1] += p * f2.y;
        }
    }

    const int part = (w << 2) + g;  // 0..31
#pragma unroll
    for (int q = 0; q < 8; q++) acc_red[part][s8 * 8 + q] = acc[q];
    __syncthreads();

    // tree reduce 32 partials -> 4 -> 1, fixed order (deterministic)
    const int f = tid & 63;
    const int c4 = tid >> 6;  // 0..3
    float sp = 0.f;
#pragma unroll
    for (int q = 0; q < 8; q++) sp += acc_red[c4 * 8 + q][f];
    fin[c4][f] = sp;
    __syncthreads();

    if (tid < OUT_F) {
        float v = (fin[0][tid] + fin[1][tid] + fin[2][tid] + fin[3][tid]) * invden_s;
        v = v > 0.f ? v : expm1f(v);  // ELU
        out[(size_t)i * OUT_F + tid] = v;
    }
}

// ---------------------------------------------------------------------------
// inputs (metadata order): h [8192,256] f32, adj [8192,8192] f32,
//                          W [256,64] f32, a [128,1] f32
// output: [8192,64] f32
// ---------------------------------------------------------------------------
extern "C" void kernel_launch(void* const* d_in, const int* in_sizes, int n_in,
                              void* d_out, int out_size) {
    const float* h   = (const float*)d_in[0];
    const float* adj = (const float*)d_in[1];
    const float* W   = (const float*)d_in[2];
    const float* a   = (const float*)d_in[3];
    float* out = (float*)d_out;

    wh_kernel<<<N_NODES, 64>>>(h, W, a);
    attn_kernel<<<N_NODES, 256>>>(adj, out);
}

// round 2
// speedup vs baseline: 1.1391x; 1.1391x over previous
#include <cuda_runtime.h>
#include <cuda_fp16.h>

#define N_NODES 8192
#define IN_F 256
#define OUT_F 64
#define ALPHA 0.3f
#define MAXNZ 1024

// Scratch (no allocations allowed): fp16 Wh (uint4 for 16B vector loads),
// src/dst attention projections.
__device__ uint4 g_Whh[N_NODES * (OUT_F * 2 / 16)];  // 8192 * 8 uint4 = 1 MB
__device__ float g_src[N_NODES];
__device__ float g_dst[N_NODES];

// ---------------------------------------------------------------------------
// Kernel 1: Wh = h @ W (fp16 out), src = Wh @ a[:64], dst = Wh @ a[64:]
// 4 rows per block, 256 threads (64 per row, one per output feature).
// ---------------------------------------------------------------------------
__global__ __launch_bounds__(256) void wh_kernel(const float* __restrict__ h,
                                                 const float* __restrict__ W,
                                                 const float* __restrict__ a) {
    __shared__ float hrow[4][IN_F];
    __shared__ float sred[4][2], dred[4][2];
    const int r = threadIdx.x >> 6;   // 0..3 row within block
    const int f = threadIdx.x & 63;   // output feature
    const int i = (blockIdx.x << 2) + r;

    // cooperative load of 4 rows: 256 threads * float4 = 1024 floats
    reinterpret_cast<float4*>(&hrow[0][0])[threadIdx.x] =
        reinterpret_cast<const float4*>(h + ((size_t)blockIdx.x << 2) * IN_F)[threadIdx.x];
    __syncthreads();

    float acc0 = 0.f, acc1 = 0.f;
#pragma unroll 4
    for (int k = 0; k < IN_F; k += 2) {
        acc0 += hrow[r][k]     * __ldg(&W[k * OUT_F + f]);
        acc1 += hrow[r][k + 1] * __ldg(&W[(k + 1) * OUT_F + f]);
    }
    const float acc = acc0 + acc1;

    reinterpret_cast<__half*>(g_Whh)[(size_t)i * OUT_F + f] = __float2half(acc);

    float sv = acc * __ldg(&a[f]);
    float dv = acc * __ldg(&a[OUT_F + f]);
#pragma unroll
    for (int o = 16; o; o >>= 1) {
        sv += __shfl_down_sync(0xffffffffu, sv, o);
        dv += __shfl_down_sync(0xffffffffu, dv, o);
    }
    const int half = (f >> 5);  // which warp of the row-group
    if ((f & 31) == 0) { sred[r][half] = sv; dred[r][half] = dv; }
    __syncthreads();
    if (f == 0) {
        g_src[i] = sred[r][0] + sred[r][1];
        g_dst[i] = dred[r][0] + dred[r][1];
    }
}

// ---------------------------------------------------------------------------
// Kernel 2: fused masked-softmax attention + aggregation + ELU.
// One block (256 threads = 8 warps) per row i.
//   A: batched float4 loads of adj (MLP=4) -> ballots -> 256-word bitmask
//   B: deterministic compaction -> nz list; logits/max/exp/sum
//   C: gather-aggregate, unrolled x2: warp handles 8 nz/iter,
//      8 lanes x uint4 (8 fp16) each, fp32 accumulate
// ---------------------------------------------------------------------------
__global__ __launch_bounds__(256) void attn_kernel(const float* __restrict__ adj,
                                                   float* __restrict__ out) {
    const int i = blockIdx.x;
    const int tid = threadIdx.x;
    const int w = tid >> 5;
    const int lane = tid & 31;

    __shared__ unsigned mask[256];
    __shared__ int wsum[8], wbase[8];
    __shared__ float fred[8];
    __shared__ int cnt_s;
    __shared__ float rowmax_s, invden_s;
    __shared__ unsigned short jlist[MAXNZ];
    __shared__ float plist[MAXNZ];
    __shared__ float acc_red[32][OUT_F];
    __shared__ float fin[4][OUT_F];

    const float srci = g_src[i];
    const float4* adj4 = reinterpret_cast<const float4*>(adj + (size_t)i * N_NODES);

    // ---- Phase A: bitmask from adj, batched loads first (MLP=4), then ballots
    // Word layout: word[((k*8 + w) << 2) | c], bit l <-> element
    //   k*1024 + w*128 + l*4 + c   (k = batch 0..7, c = float4 component)
#pragma unroll
    for (int half = 0; half < 2; half++) {
        float4 v[4];
#pragma unroll
        for (int q = 0; q < 4; q++)
            v[q] = __ldg(&adj4[(half * 4 + q) * 256 + tid]);
#pragma unroll
        for (int q = 0; q < 4; q++) {
            const int k = half * 4 + q;
            const unsigned b0 = __ballot_sync(0xffffffffu, v[q].x != 0.f);
            const unsigned b1 = __ballot_sync(0xffffffffu, v[q].y != 0.f);
            const unsigned b2 = __ballot_sync(0xffffffffu, v[q].z != 0.f);
            const unsigned b3 = __ballot_sync(0xffffffffu, v[q].w != 0.f);
            if (lane == 0) {
                const int wi = (k * 8 + w) << 2;
                mask[wi + 0] = b0; mask[wi + 1] = b1;
                mask[wi + 2] = b2; mask[wi + 3] = b3;
            }
        }
    }
    __syncthreads();

    // ---- deterministic compaction: exclusive scan of per-word popcounts ----
    const unsigned myword = mask[tid];
    const int c = __popc(myword);
    int incl = c;
#pragma unroll
    for (int o = 1; o < 32; o <<= 1) {
        const int x = __shfl_up_sync(0xffffffffu, incl, o);
        if (lane >= o) incl += x;
    }
    if (lane == 31) wsum[w] = incl;
    __syncthreads();
    if (tid == 0) {
        int run = 0;
        for (int q = 0; q < 8; q++) { wbase[q] = run; run += wsum[q]; }
        cnt_s = run < MAXNZ ? run : MAXNZ;
    }
    __syncthreads();
    {
        // word tid: k = tid>>5, w' = (tid>>2)&7, comp = tid&3
        const int basej = ((tid >> 5) << 10) + (((tid >> 2) & 7) << 7) + (tid & 3);
        int off = wbase[w] + incl - c;
        unsigned m = myword;
        while (m) {
            const int b = __ffs(m) - 1;
            m &= m - 1;
            if (off < MAXNZ) jlist[off] = (unsigned short)(basej + (b << 2));
            off++;
        }
    }
    __syncthreads();
    const int cnt = cnt_s;

    // ---- Phase B1: logits + row max ----
    float lmax = -3.0e38f;
    for (int idx = tid; idx < cnt; idx += 256) {
        const int j = jlist[idx];
        float e = srci + __ldg(&g_dst[j]);
        e = e > 0.f ? e : ALPHA * e;
        plist[idx] = e;
        lmax = fmaxf(lmax, e);
    }
#pragma unroll
    for (int o = 16; o; o >>= 1) lmax = fmaxf(lmax, __shfl_xor_sync(0xffffffffu, lmax, o));
    if (lane == 0) fred[w] = lmax;
    __syncthreads();
    if (tid == 0) {
        float mm = fred[0];
        for (int q = 1; q < 8; q++) mm = fmaxf(mm, fred[q]);
        rowmax_s = mm;
    }
    __syncthreads();
    const float rowmax = rowmax_s;

    // ---- Phase B2: exp + denom ----
    float lsum = 0.f;
    for (int idx = tid; idx < cnt; idx += 256) {
        const float p = __expf(plist[idx] - rowmax);
        plist[idx] = p;
        lsum += p;
    }
#pragma unroll
    for (int o = 16; o; o >>= 1) lsum += __shfl_xor_sync(0xffffffffu, lsum, o);
    if (lane == 0) fred[w] = lsum;
    __syncthreads();
    if (tid == 0) {
        float s = 0.f;
        for (int q = 0; q < 8; q++) s += fred[q];
        invden_s = 1.f / s;
    }
    __syncthreads();

    // ---- Phase C: h' = sum_j p_j * Wh[j]  (fp16 gather, fp32 acc, unroll x2)
    const int g = lane >> 3;   // 4 nz-groups per warp
    const int s8 = lane & 7;   // 8 lanes x 8 halves = 64 features
    float acc[8];
#pragma unroll
    for (int q = 0; q < 8; q++) acc[q] = 0.f;

    for (int base = (w << 2); base < cnt; base += 64) {
        const int idx0 = base + g;
        const int idx1 = base + 32 + g;
        float p0 = 0.f, p1 = 0.f;
        int j0 = 0, j1 = 0;
        if (idx0 < cnt) { p0 = plist[idx0]; j0 = jlist[idx0]; }
        if (idx1 < cnt) { p1 = plist[idx1]; j1 = jlist[idx1]; }
        const uint4 v0 = __ldg(&g_Whh[j0 * 8 + s8]);
        const uint4 v1 = __ldg(&g_Whh[j1 * 8 + s8]);
        const __half2* h0 = reinterpret_cast<const __half2*>(&v0);
        const __half2* h1 = reinterpret_cast<const __half2*>(&v1);
#pragma unroll
        for (int q = 0; q < 4; q++) {
            const float2 f0 = __half22float2(h0[q]);
            const float2 f1 = __half22float2(h1[q]);
            acc[2 * q]     += p0 * f0.x + p1 * f1.x;
            acc[2 * q + 1] += p0 * f0.y + p1 * f1.y;
        }
    }

    const int part = (w << 2) + g;  // 0..31
#pragma unroll
    for (int q = 0; q < 8; q++) acc_red[part][s8 * 8 + q] = acc[q];
    __syncthreads();

    // tree reduce 32 partials -> 4 -> 1, fixed order (deterministic)
    const int f = tid & 63;
    const int c4 = tid >> 6;  // 0..3
    float sp = 0.f;
#pragma unroll
    for (int q = 0; q < 8; q++) sp += acc_red[c4 * 8 + q][f];
    fin[c4][f] = sp;
    __syncthreads();

    if (tid < OUT_F) {
        float v = (fin[0][tid] + fin[1][tid] + fin[2][tid] + fin[3][tid]) * invden_s;
        v = v > 0.f ? v : expm1f(v);  // ELU
        out[(size_t)i * OUT_F + tid] = v;
    }
}

// ---------------------------------------------------------------------------
// inputs (metadata order): h [8192,256] f32, adj [8192,8192] f32,
//                          W [256,64] f32, a [128,1] f32
// output: [8192,64] f32
// ---------------------------------------------------------------------------
extern "C" void kernel_launch(void* const* d_in, const int* in_sizes, int n_in,
                              void* d_out, int out_size) {
    const float* h   = (const float*)d_in[0];
    const float* adj = (const float*)d_in[1];
    const float* W   = (const float*)d_in[2];
    const float* a   = (const float*)d_in[3];
    float* out = (float*)d_out;

    wh_kernel<<<N_NODES / 4, 256>>>(h, W, a);
    attn_kernel<<<N_NODES, 256>>>(adj, out);
}